// round 13
// baseline (speedup 1.0000x reference)
#include <cuda_runtime.h>
#include <cuda_bf16.h>
#include <math.h>
#include <mma.h>

using namespace nvcuda;

#define Bv 4
#define Tv 2048
#define Cv 1024
#define Hv 16
#define HDv 64
#define Mv (Bv * Tv)
#define QKV_N (3 * Cv)

__device__ float g_qkv[Mv * QKV_N];
__device__ float g_rope[2 * Tv * 32];
// pre-split bf16 operands for GEMMs
__device__ __nv_bfloat16 g_ah[Mv * Cv];
__device__ __nv_bfloat16 g_al[Mv * Cv];
__device__ __nv_bfloat16 g_wh[4 * Cv * Cv];
__device__ __nv_bfloat16 g_wl[4 * Cv * Cv];
// pre-split bf16 qkv (post norm+rope) for flash
__device__ __nv_bfloat16 g_qkvh[Mv * QKV_N];
__device__ __nv_bfloat16 g_qkvl[Mv * QKV_N];

// ---------------------------------------------------------------------------
__global__ void rope_table_kernel(float* __restrict__ rope)
{
    int idx = blockIdx.x * blockDim.x + threadIdx.x;
    if (idx >= Tv * 32) return;
    int t = idx >> 5;
    int i = idx & 31;
    double inv_freq_d = exp(-(double)i * (9.210340371976184 / 32.0));
    float inv_freq = (float)inv_freq_d;
    float ang = (float)t * inv_freq;
    float cf = (float)cos((double)ang);
    float sf = (float)sin((double)ang);
    rope[idx] = __bfloat162float(__float2bfloat16(cf));
    rope[Tv * 32 + idx] = __bfloat162float(__float2bfloat16(sf));
}

// ---------------------------------------------------------------------------
__device__ __forceinline__ void bpack4(const float4 v, uint2& h, uint2& l)
{
    __nv_bfloat162 h0 = __floats2bfloat162_rn(v.x, v.y);
    __nv_bfloat162 h1 = __floats2bfloat162_rn(v.z, v.w);
    __nv_bfloat162 l0 = __floats2bfloat162_rn(v.x - __bfloat162float(h0.x),
                                              v.y - __bfloat162float(h0.y));
    __nv_bfloat162 l1 = __floats2bfloat162_rn(v.z - __bfloat162float(h1.x),
                                              v.w - __bfloat162float(h1.y));
    h.x = *(unsigned*)&h0; h.y = *(unsigned*)&h1;
    l.x = *(unsigned*)&l0; l.y = *(unsigned*)&l1;
}

__device__ __forceinline__ void packsplit(float a, float b, unsigned& h, unsigned& l)
{
    __nv_bfloat16 ha = __float2bfloat16(a);
    __nv_bfloat16 hb = __float2bfloat16(b);
    __nv_bfloat162 hh;
    hh.x = ha; hh.y = hb;
    __nv_bfloat162 ll;
    ll.x = __float2bfloat16(a - __bfloat162float(ha));
    ll.y = __float2bfloat16(b - __bfloat162float(hb));
    h = *(unsigned*)&hh;
    l = *(unsigned*)&ll;
}

__device__ __forceinline__ void split1(float a,
                                       __nv_bfloat16* __restrict__ h,
                                       __nv_bfloat16* __restrict__ l)
{
    __nv_bfloat16 hi = __float2bfloat16(a);
    *h = hi;
    *l = __float2bfloat16(a - __bfloat162float(hi));
}

// fp32 -> bf16 hi/lo pack (elementwise, 4 at a time)
__global__ void pack_split_kernel(const float* __restrict__ in,
                                  __nv_bfloat16* __restrict__ h,
                                  __nv_bfloat16* __restrict__ l, int n4)
{
    int i = blockIdx.x * blockDim.x + threadIdx.x;
    if (i >= n4) return;
    float4 v = ((const float4*)in)[i];
    uint2 hp;
    uint2 lp;
    bpack4(v, hp, lp);
    ((uint2*)h)[i] = hp;
    ((uint2*)l)[i] = lp;
}

// ---------------------------------------------------------------------------
__device__ __forceinline__ void ldsm4(unsigned addr, unsigned* r)
{
    asm volatile("ldmatrix.sync.aligned.m8n8.x4.shared.b16 { %0, %1, %2, %3 }, [ %4 ];"
                 : "=r"(r[0]), "=r"(r[1]), "=r"(r[2]), "=r"(r[3]) : "r"(addr));
}
__device__ __forceinline__ void ldsm4t(unsigned addr, unsigned* r)
{
    asm volatile("ldmatrix.sync.aligned.m8n8.x4.trans.shared.b16 { %0, %1, %2, %3 }, [ %4 ];"
                 : "=r"(r[0]), "=r"(r[1]), "=r"(r[2]), "=r"(r[3]) : "r"(addr));
}
__device__ __forceinline__ void mma_bf16(float* c, const unsigned* a,
                                         unsigned b0, unsigned b1)
{
    asm volatile("mma.sync.aligned.m16n8k16.row.col.f32.bf16.bf16.f32 "
                 "{ %0, %1, %2, %3 }, { %4, %5, %6, %7 }, { %8, %9 }, { %0, %1, %2, %3 };"
                 : "+f"(c[0]), "+f"(c[1]), "+f"(c[2]), "+f"(c[3])
                 : "r"(a[0]), "r"(a[1]), "r"(a[2]), "r"(a[3]), "r"(b0), "r"(b1));
}
__device__ __forceinline__ void cp16(unsigned dst, const void* src)
{
    asm volatile("cp.async.cg.shared.global [ %0 ], [ %1 ], 16;" :: "r"(dst), "l"(src));
}
__device__ __forceinline__ void cpcommit()
{
    asm volatile("cp.async.commit_group;");
}
__device__ __forceinline__ void cpwait0()
{
    asm volatile("cp.async.wait_group 0;");
}
__device__ __forceinline__ void cpwait1()
{
    asm volatile("cp.async.wait_group 1;");
}

// ---------------------------------------------------------------------------
// GEMM (NT): 3-term emulated fp32, pre-split bf16, cp.async 2-stage.
// BM=256, BN=128, BK=32. 8 warps as 4x2; warp tile 64x64 (4x4 wmma tiles):
// 16 fragment loads per 48 mmas per k-step.
// ---------------------------------------------------------------------------
__global__ void __launch_bounds__(256) gemm_bf16_pre(
    const __nv_bfloat16* __restrict__ Ah, const __nv_bfloat16* __restrict__ Al,
    const __nv_bfloat16* __restrict__ Bh, const __nv_bfloat16* __restrict__ Bl,
    float* __restrict__ C, int M, int N, int K)
{
    constexpr int BM = 256, BN = 128, BK = 32, LD = 40;
    constexpr int STG = (2 * BM + 2 * BN) * LD;   // bf16 elems per stage
    extern __shared__ __align__(16) char smraw[];
    __nv_bfloat16* sm = (__nv_bfloat16*)smraw;
    const unsigned smS = (unsigned)__cvta_generic_to_shared(sm);

    const int tid = threadIdx.x;
    const int m0 = blockIdx.y * BM;
    const int n0 = blockIdx.x * BN;
    const int w = tid >> 5;
    const int wm = w >> 1;    // 0..3 -> 64 rows each
    const int wn = w & 1;     // 0..1 -> 64 cols each

    wmma::fragment<wmma::accumulator, 16, 16, 16, float> acc[4][4];
#pragma unroll
    for (int i = 0; i < 4; i++)
#pragma unroll
        for (int j = 0; j < 4; j++)
            wmma::fill_fragment(acc[i][j], 0.0f);

    const int nk = K / BK;

    // stage layout (bf16 elems): Ah[BM*LD] Al[BM*LD] Bh[BN*LD] Bl[BN*LD]
#define LOAD_STAGE(stg, k0)                                                   \
    do {                                                                      \
        unsigned sb = smS + (unsigned)((stg) * STG * 2);                      \
        for (int c = tid; c < BM * 4; c += 256) {                             \
            int r = c >> 2;                                                   \
            int coff = (c & 3) * 8;                                           \
            unsigned so = (unsigned)((r * LD + coff) * 2);                    \
            cp16(sb + so, Ah + (size_t)(m0 + r) * K + (k0) + coff);           \
            cp16(sb + (unsigned)(BM * LD * 2) + so,                           \
                 Al + (size_t)(m0 + r) * K + (k0) + coff);                    \
        }                                                                     \
        for (int c = tid; c < BN * 4; c += 256) {                             \
            int r = c >> 2;                                                   \
            int coff = (c & 3) * 8;                                           \
            unsigned so = (unsigned)((r * LD + coff) * 2);                    \
            cp16(sb + (unsigned)(2 * BM * LD * 2) + so,                       \
                 Bh + (size_t)(n0 + r) * K + (k0) + coff);                    \
            cp16(sb + (unsigned)((2 * BM + BN) * LD * 2) + so,                \
                 Bl + (size_t)(n0 + r) * K + (k0) + coff);                    \
        }                                                                     \
    } while (0)

    LOAD_STAGE(0, 0);
    cpcommit();

    for (int kt = 0; kt < nk; kt++) {
        if (kt + 1 < nk) {
            LOAD_STAGE((kt + 1) & 1, (kt + 1) * BK);
            cpcommit();
            cpwait1();
        } else {
            cpwait0();
        }
        __syncthreads();

        __nv_bfloat16* sAh = sm + (kt & 1) * STG;
        __nv_bfloat16* sAl = sAh + BM * LD;
        __nv_bfloat16* sBh = sAl + BM * LD;
        __nv_bfloat16* sBl = sBh + BN * LD;

#pragma unroll
        for (int kk = 0; kk < BK; kk += 16) {
            wmma::fragment<wmma::matrix_a, 16, 16, 16, __nv_bfloat16, wmma::row_major> afh[4];
            wmma::fragment<wmma::matrix_a, 16, 16, 16, __nv_bfloat16, wmma::row_major> afl[4];
            wmma::fragment<wmma::matrix_b, 16, 16, 16, __nv_bfloat16, wmma::col_major> bfh[4];
            wmma::fragment<wmma::matrix_b, 16, 16, 16, __nv_bfloat16, wmma::col_major> bfl[4];
#pragma unroll
            for (int i = 0; i < 4; i++) {
                wmma::load_matrix_sync(afh[i], &sAh[(wm * 64 + i * 16) * LD + kk], LD);
                wmma::load_matrix_sync(afl[i], &sAl[(wm * 64 + i * 16) * LD + kk], LD);
            }
#pragma unroll
            for (int j = 0; j < 4; j++) {
                wmma::load_matrix_sync(bfh[j], &sBh[(wn * 64 + j * 16) * LD + kk], LD);
                wmma::load_matrix_sync(bfl[j], &sBl[(wn * 64 + j * 16) * LD + kk], LD);
            }
#pragma unroll
            for (int i = 0; i < 4; i++)
#pragma unroll
                for (int j = 0; j < 4; j++) {
                    wmma::mma_sync(acc[i][j], afh[i], bfl[j], acc[i][j]);
                    wmma::mma_sync(acc[i][j], afl[i], bfh[j], acc[i][j]);
                    wmma::mma_sync(acc[i][j], afh[i], bfh[j], acc[i][j]);
                }
        }
        __syncthreads();
    }
#undef LOAD_STAGE

#pragma unroll
    for (int i = 0; i < 4; i++)
#pragma unroll
        for (int j = 0; j < 4; j++)
            wmma::store_matrix_sync(
                C + (size_t)(m0 + wm * 64 + i * 16) * N + n0 + wn * 64 + j * 16,
                acc[i][j], N, wmma::mem_row_major);
}

// ---------------------------------------------------------------------------
// Fused RMSNorm + rope on q,k AND hi/lo bf16 pack of q,k,v.
// ---------------------------------------------------------------------------
__global__ void __launch_bounds__(512) norm_rope_pack_kernel(
    const float* __restrict__ qkv, const float* __restrict__ rope,
    __nv_bfloat16* __restrict__ qh, __nv_bfloat16* __restrict__ ql)
{
    const int bt = blockIdx.x;
    const int t = bt & (Tv - 1);
    const int warp = threadIdx.x >> 5;
    const int lane = threadIdx.x & 31;

    const size_t base = (size_t)bt * QKV_N + warp * HDv;
    float c = rope[t * 32 + lane];
    float s = rope[Tv * 32 + t * 32 + lane];

#pragma unroll
    for (int p = 0; p < 2; p++) {   // q, k
        const float* ptr = qkv + base + p * Cv;
        float x1 = ptr[lane];
        float x2 = ptr[lane + 32];
        float ss = x1 * x1 + x2 * x2;
#pragma unroll
        for (int off = 16; off; off >>= 1)
            ss += __shfl_xor_sync(0xffffffffu, ss, off);
        float r = rsqrtf(ss * (1.0f / 64.0f) + 1.1920929e-07f);
        x1 *= r;
        x2 *= r;
        float y1 = x1 * c + x2 * s;
        float y2 = -x1 * s + x2 * c;
        split1(y1, qh + base + p * Cv + lane, ql + base + p * Cv + lane);
        split1(y2, qh + base + p * Cv + lane + 32, ql + base + p * Cv + lane + 32);
    }
    {
        const float* ptr = qkv + base + 2 * Cv;
        float v1 = ptr[lane];
        float v2 = ptr[lane + 32];
        split1(v1, qh + base + 2 * Cv + lane, ql + base + 2 * Cv + lane);
        split1(v2, qh + base + 2 * Cv + lane + 32, ql + base + 2 * Cv + lane + 32);
    }
}

// ---------------------------------------------------------------------------
// Flash attention: raw mma 3xBF16, register S/O, pre-split inputs,
// cp.async 2-stage K/V. Epilogue writes y pre-split into ah/al (for proj).
// ---------------------------------------------------------------------------
__global__ void __launch_bounds__(256) flash_mma_kernel(
    const __nv_bfloat16* __restrict__ qh, const __nv_bfloat16* __restrict__ ql,
    __nv_bfloat16* __restrict__ yh, __nv_bfloat16* __restrict__ yl)
{
    constexpr int LDB = 72;
    constexpr int KVSTG = 4 * 64 * LDB;
    extern __shared__ __align__(16) char smraw[];
    __nv_bfloat16* Qh = (__nv_bfloat16*)smraw;
    __nv_bfloat16* Ql = Qh + 128 * LDB;
    __nv_bfloat16* KV = Ql + 128 * LDB;

    const int qt = gridDim.x - 1 - blockIdx.x;
    const int bh = blockIdx.y;
    const int b = bh / Hv;
    const int h = bh % Hv;
    const int tid = threadIdx.x;
    const int wid = tid >> 5;
    const int lane = tid & 31;
    const int gid = lane >> 2;
    const int tig = lane & 3;

    const size_t rowbase = (size_t)b * Tv;
    const int q0 = qt * 128;

    const int arow = (lane & 7) + 8 * ((lane >> 3) & 1);
    const int acolo = 8 * (lane >> 4);
    const int brow = (lane & 7) + 8 * (lane >> 4);
    const int bcolo = 8 * ((lane >> 3) & 1);

    const unsigned QhS = (unsigned)__cvta_generic_to_shared(Qh);
    const unsigned QlS = (unsigned)__cvta_generic_to_shared(Ql);
    const unsigned KVS = (unsigned)__cvta_generic_to_shared(KV);

    float sc[8][4];
    float oc[8][4];
    unsigned qa[4];
    unsigned qb[4];
    unsigned ka[4];
    unsigned kb[4];
    unsigned va[4];
    unsigned vb[4];
    unsigned pah[4][4];
    unsigned pal[4][4];
    float mrow[2];
    float lrow[2];

#define LOAD_KV(stg, jt)                                                      \
    do {                                                                      \
        unsigned sb = KVS + (unsigned)((stg) * KVSTG * 2);                    \
        const __nv_bfloat16* gkh = qh + (rowbase + (jt) * 64) * (size_t)QKV_N + Cv + h * HDv; \
        const __nv_bfloat16* gkl = ql + (rowbase + (jt) * 64) * (size_t)QKV_N + Cv + h * HDv; \
        for (int c = tid; c < 512; c += 256) {                                \
            int r = c >> 3;                                                   \
            int co = (c & 7) * 8;                                             \
            unsigned off = (unsigned)((r * LDB + co) * 2);                    \
            cp16(sb + off, gkh + (size_t)r * QKV_N + co);                     \
            cp16(sb + (unsigned)(64 * LDB * 2) + off, gkl + (size_t)r * QKV_N + co); \
            cp16(sb + (unsigned)(2 * 64 * LDB * 2) + off, gkh + (size_t)r * QKV_N + Cv + co); \
            cp16(sb + (unsigned)(3 * 64 * LDB * 2) + off, gkl + (size_t)r * QKV_N + Cv + co); \
        }                                                                     \
    } while (0)

    for (int c = tid; c < 1024; c += 256) {
        int r = c >> 3;
        int co = (c & 7) * 8;
        unsigned off = (unsigned)((r * LDB + co) * 2);
        cp16(QhS + off, qh + (rowbase + q0 + r) * (size_t)QKV_N + h * HDv + co);
        cp16(QlS + off, ql + (rowbase + q0 + r) * (size_t)QKV_N + h * HDv + co);
    }
    LOAD_KV(0, 0);
    cpcommit();

#pragma unroll
    for (int j = 0; j < 8; j++)
#pragma unroll
        for (int k = 0; k < 4; k++) oc[j][k] = 0.0f;

    mrow[0] = -1e30f;
    mrow[1] = -1e30f;
    lrow[0] = 0.0f;
    lrow[1] = 0.0f;
    const int r0g = q0 + wid * 16 + gid;
    const int r1g = r0g + 8;

    const int jt_max = 2 * qt + 1;
    for (int jt = 0; jt <= jt_max; jt++) {
        if (jt < jt_max) {
            LOAD_KV((jt + 1) & 1, jt + 1);
            cpcommit();
            cpwait1();
        } else {
            cpwait0();
        }
        __syncthreads();

        unsigned sb = KVS + (unsigned)((jt & 1) * KVSTG * 2);
        unsigned KhC = sb;
        unsigned KlC = sb + (unsigned)(64 * LDB * 2);
        unsigned VhC = sb + (unsigned)(2 * 64 * LDB * 2);
        unsigned VlC = sb + (unsigned)(3 * 64 * LDB * 2);

#pragma unroll
        for (int j = 0; j < 8; j++)
#pragma unroll
            for (int k = 0; k < 4; k++) sc[j][k] = 0.0f;

#pragma unroll
        for (int t = 0; t < 4; t++) {
            unsigned qoff = (unsigned)(((wid * 16 + arow) * LDB + t * 16 + acolo) * 2);
            ldsm4(QhS + qoff, qa);
            ldsm4(QlS + qoff, qb);
#pragma unroll
            for (int g = 0; g < 4; g++) {
                unsigned koff = (unsigned)(((g * 16 + brow) * LDB + t * 16 + bcolo) * 2);
                ldsm4(KhC + koff, ka);
                ldsm4(KlC + koff, kb);
                mma_bf16(sc[2 * g], qa, kb[0], kb[1]);
                mma_bf16(sc[2 * g], qb, ka[0], ka[1]);
                mma_bf16(sc[2 * g], qa, ka[0], ka[1]);
                mma_bf16(sc[2 * g + 1], qa, kb[2], kb[3]);
                mma_bf16(sc[2 * g + 1], qb, ka[2], ka[3]);
                mma_bf16(sc[2 * g + 1], qa, ka[2], ka[3]);
            }
        }

        const bool maskp = (jt >= 2 * qt);
        float mt0 = -1e30f;
        float mt1 = -1e30f;
#pragma unroll
        for (int j = 0; j < 8; j++) {
            int c0 = jt * 64 + j * 8 + tig * 2;
            sc[j][0] *= 0.125f;
            sc[j][1] *= 0.125f;
            sc[j][2] *= 0.125f;
            sc[j][3] *= 0.125f;
            if (maskp) {
                if (c0 > r0g) sc[j][0] = -1e30f;
                if (c0 + 1 > r0g) sc[j][1] = -1e30f;
                if (c0 > r1g) sc[j][2] = -1e30f;
                if (c0 + 1 > r1g) sc[j][3] = -1e30f;
            }
            mt0 = fmaxf(mt0, fmaxf(sc[j][0], sc[j][1]));
            mt1 = fmaxf(mt1, fmaxf(sc[j][2], sc[j][3]));
        }
        mt0 = fmaxf(mt0, __shfl_xor_sync(0xffffffffu, mt0, 1));
        mt0 = fmaxf(mt0, __shfl_xor_sync(0xffffffffu, mt0, 2));
        mt1 = fmaxf(mt1, __shfl_xor_sync(0xffffffffu, mt1, 1));
        mt1 = fmaxf(mt1, __shfl_xor_sync(0xffffffffu, mt1, 2));

        float mn0 = fmaxf(mrow[0], mt0);
        float mn1 = fmaxf(mrow[1], mt1);
        float corr0 = expf(mrow[0] - mn0);
        float corr1 = expf(mrow[1] - mn1);

        float s0 = 0.0f;
        float s1 = 0.0f;
#pragma unroll
        for (int t = 0; t < 4; t++) {
            float p00 = expf(sc[2 * t][0] - mn0);
            float p01 = expf(sc[2 * t][1] - mn0);
            float p02 = expf(sc[2 * t][2] - mn1);
            float p03 = expf(sc[2 * t][3] - mn1);
            float p10 = expf(sc[2 * t + 1][0] - mn0);
            float p11 = expf(sc[2 * t + 1][1] - mn0);
            float p12 = expf(sc[2 * t + 1][2] - mn1);
            float p13 = expf(sc[2 * t + 1][3] - mn1);
            s0 += p00 + p01 + p10 + p11;
            s1 += p02 + p03 + p12 + p13;
            packsplit(p00, p01, pah[t][0], pal[t][0]);
            packsplit(p02, p03, pah[t][1], pal[t][1]);
            packsplit(p10, p11, pah[t][2], pal[t][2]);
            packsplit(p12, p13, pah[t][3], pal[t][3]);
        }
        s0 += __shfl_xor_sync(0xffffffffu, s0, 1);
        s0 += __shfl_xor_sync(0xffffffffu, s0, 2);
        s1 += __shfl_xor_sync(0xffffffffu, s1, 1);
        s1 += __shfl_xor_sync(0xffffffffu, s1, 2);

        lrow[0] = lrow[0] * corr0 + s0;
        lrow[1] = lrow[1] * corr1 + s1;
        mrow[0] = mn0;
        mrow[1] = mn1;
#pragma unroll
        for (int j = 0; j < 8; j++) {
            oc[j][0] *= corr0;
            oc[j][1] *= corr0;
            oc[j][2] *= corr1;
            oc[j][3] *= corr1;
        }

#pragma unroll
        for (int t = 0; t < 4; t++) {
#pragma unroll
            for (int n = 0; n < 4; n++) {
                unsigned voff = (unsigned)(((t * 16 + arow) * LDB + n * 16 + acolo) * 2);
                ldsm4t(VhC + voff, va);
                ldsm4t(VlC + voff, vb);
                mma_bf16(oc[2 * n], pah[t], vb[0], vb[1]);
                mma_bf16(oc[2 * n], pal[t], va[0], va[1]);
                mma_bf16(oc[2 * n], pah[t], va[0], va[1]);
                mma_bf16(oc[2 * n + 1], pah[t], vb[2], vb[3]);
                mma_bf16(oc[2 * n + 1], pal[t], va[2], va[3]);
                mma_bf16(oc[2 * n + 1], pah[t], va[2], va[3]);
            }
        }
        __syncthreads();
    }
#undef LOAD_KV

    // Epilogue: normalize and write y pre-split (hi/lo) for the proj GEMM.
    float i0 = 1.0f / lrow[0];
    float i1 = 1.0f / lrow[1];
#pragma unroll
    for (int j = 0; j < 8; j++) {
        int col = h * HDv + j * 8 + tig * 2;
        size_t idx0 = (rowbase + r0g) * (size_t)Cv + col;
        size_t idx1 = (rowbase + r1g) * (size_t)Cv + col;
        split1(oc[j][0] * i0, yh + idx0, yl + idx0);
        split1(oc[j][1] * i0, yh + idx0 + 1, yl + idx0 + 1);
        split1(oc[j][2] * i1, yh + idx1, yl + idx1);
        split1(oc[j][3] * i1, yh + idx1 + 1, yl + idx1 + 1);
    }
}

// ---------------------------------------------------------------------------
extern "C" void kernel_launch(void* const* d_in, const int* in_sizes, int n_in,
                              void* d_out, int out_size)
{
    const float* x = (const float*)d_in[0];
    const float* w_attn = (const float*)d_in[1];
    const float* w_proj = (const float*)d_in[2];
    float* out = (float*)d_out;

    float* qkv_p = nullptr;
    float* rope_p = nullptr;
    __nv_bfloat16* ah_p = nullptr;
    __nv_bfloat16* al_p = nullptr;
    __nv_bfloat16* wh_p = nullptr;
    __nv_bfloat16* wl_p = nullptr;
    __nv_bfloat16* qh_p = nullptr;
    __nv_bfloat16* ql_p = nullptr;
    cudaGetSymbolAddress((void**)&qkv_p, g_qkv);
    cudaGetSymbolAddress((void**)&rope_p, g_rope);
    cudaGetSymbolAddress((void**)&ah_p, g_ah);
    cudaGetSymbolAddress((void**)&al_p, g_al);
    cudaGetSymbolAddress((void**)&wh_p, g_wh);
    cudaGetSymbolAddress((void**)&wl_p, g_wl);
    cudaGetSymbolAddress((void**)&qh_p, g_qkvh);
    cudaGetSymbolAddress((void**)&ql_p, g_qkvl);

    const int GEMM_SMEM = 2 * (2 * 256 + 2 * 128) * 40 * (int)sizeof(__nv_bfloat16);  // 122880 B
    cudaFuncSetAttribute(gemm_bf16_pre, cudaFuncAttributeMaxDynamicSharedMemorySize, GEMM_SMEM);

    rope_table_kernel<<<(Tv * 32 + 255) / 256, 256>>>(rope_p);

    pack_split_kernel<<<(Mv * Cv / 4 + 255) / 256, 256>>>(x, ah_p, al_p, Mv * Cv / 4);
    pack_split_kernel<<<(QKV_N * Cv / 4 + 255) / 256, 256>>>(w_attn, wh_p, wl_p, QKV_N * Cv / 4);
    pack_split_kernel<<<(Cv * Cv / 4 + 255) / 256, 256>>>(
        w_proj, wh_p + QKV_N * Cv, wl_p + QKV_N * Cv, Cv * Cv / 4);

    // qkv = x @ w_attn^T
    gemm_bf16_pre<<<dim3(QKV_N / 128, Mv / 256), 256, GEMM_SMEM>>>(
        ah_p, al_p, wh_p, wl_p, qkv_p, Mv, QKV_N, Cv);

    // norm + rope + split pack of q,k,v
    norm_rope_pack_kernel<<<Mv, 512>>>(qkv_p, rope_p, qh_p, ql_p);

    // flash -> writes y pre-split into ah/al
    const int FLASH_SMEM = (2 * 128 * 72 + 8 * 64 * 72) * (int)sizeof(__nv_bfloat16);  // 110592 B
    cudaFuncSetAttribute(flash_mma_kernel, cudaFuncAttributeMaxDynamicSharedMemorySize, FLASH_SMEM);
    flash_mma_kernel<<<dim3(Tv / 128, Bv * Hv), 256, FLASH_SMEM>>>(qh_p, ql_p, ah_p, al_p);

    // out = y @ w_proj^T
    gemm_bf16_pre<<<dim3(Cv / 128, Mv / 256), 256, GEMM_SMEM>>>(
        ah_p, al_p, wh_p + QKV_N * Cv, wl_p + QKV_N * Cv, out, Mv, Cv, Cv);
}

// round 15
// speedup vs baseline: 1.0968x; 1.0968x over previous
#include <cuda_runtime.h>
#include <cuda_bf16.h>
#include <math.h>
#include <mma.h>

using namespace nvcuda;

#define Bv 4
#define Tv 2048
#define Cv 1024
#define Hv 16
#define HDv 64
#define Mv (Bv * Tv)
#define QKV_N (3 * Cv)

__device__ float g_qkv[Mv * QKV_N];
__device__ float g_rope[2 * Tv * 32];
// pre-split bf16 operands for GEMMs
__device__ __nv_bfloat16 g_ah[Mv * Cv];
__device__ __nv_bfloat16 g_al[Mv * Cv];
__device__ __nv_bfloat16 g_wh[4 * Cv * Cv];
__device__ __nv_bfloat16 g_wl[4 * Cv * Cv];
// pre-split bf16 qkv (post norm+rope) for flash
__device__ __nv_bfloat16 g_qkvh[Mv * QKV_N];
__device__ __nv_bfloat16 g_qkvl[Mv * QKV_N];

// ---------------------------------------------------------------------------
__global__ void rope_table_kernel(float* __restrict__ rope)
{
    int idx = blockIdx.x * blockDim.x + threadIdx.x;
    if (idx >= Tv * 32) return;
    int t = idx >> 5;
    int i = idx & 31;
    double inv_freq_d = exp(-(double)i * (9.210340371976184 / 32.0));
    float inv_freq = (float)inv_freq_d;
    float ang = (float)t * inv_freq;
    float cf = (float)cos((double)ang);
    float sf = (float)sin((double)ang);
    rope[idx] = __bfloat162float(__float2bfloat16(cf));
    rope[Tv * 32 + idx] = __bfloat162float(__float2bfloat16(sf));
}

// ---------------------------------------------------------------------------
__device__ __forceinline__ void bpack4(const float4 v, uint2& h, uint2& l)
{
    __nv_bfloat162 h0 = __floats2bfloat162_rn(v.x, v.y);
    __nv_bfloat162 h1 = __floats2bfloat162_rn(v.z, v.w);
    __nv_bfloat162 l0 = __floats2bfloat162_rn(v.x - __bfloat162float(h0.x),
                                              v.y - __bfloat162float(h0.y));
    __nv_bfloat162 l1 = __floats2bfloat162_rn(v.z - __bfloat162float(h1.x),
                                              v.w - __bfloat162float(h1.y));
    h.x = *(unsigned*)&h0; h.y = *(unsigned*)&h1;
    l.x = *(unsigned*)&l0; l.y = *(unsigned*)&l1;
}

__device__ __forceinline__ void packsplit(float a, float b, unsigned& h, unsigned& l)
{
    __nv_bfloat16 ha = __float2bfloat16(a);
    __nv_bfloat16 hb = __float2bfloat16(b);
    __nv_bfloat162 hh;
    hh.x = ha; hh.y = hb;
    __nv_bfloat162 ll;
    ll.x = __float2bfloat16(a - __bfloat162float(ha));
    ll.y = __float2bfloat16(b - __bfloat162float(hb));
    h = *(unsigned*)&hh;
    l = *(unsigned*)&ll;
}

__device__ __forceinline__ void split1(float a,
                                       __nv_bfloat16* __restrict__ h,
                                       __nv_bfloat16* __restrict__ l)
{
    __nv_bfloat16 hi = __float2bfloat16(a);
    *h = hi;
    *l = __float2bfloat16(a - __bfloat162float(hi));
}

// fp32 -> bf16 hi/lo pack (elementwise, 4 at a time)
__global__ void pack_split_kernel(const float* __restrict__ in,
                                  __nv_bfloat16* __restrict__ h,
                                  __nv_bfloat16* __restrict__ l, int n4)
{
    int i = blockIdx.x * blockDim.x + threadIdx.x;
    if (i >= n4) return;
    float4 v = ((const float4*)in)[i];
    uint2 hp;
    uint2 lp;
    bpack4(v, hp, lp);
    ((uint2*)h)[i] = hp;
    ((uint2*)l)[i] = lp;
}

// ---------------------------------------------------------------------------
__device__ __forceinline__ void ldsm4(unsigned addr, unsigned* r)
{
    asm volatile("ldmatrix.sync.aligned.m8n8.x4.shared.b16 { %0, %1, %2, %3 }, [ %4 ];"
                 : "=r"(r[0]), "=r"(r[1]), "=r"(r[2]), "=r"(r[3]) : "r"(addr));
}
__device__ __forceinline__ void ldsm4t(unsigned addr, unsigned* r)
{
    asm volatile("ldmatrix.sync.aligned.m8n8.x4.trans.shared.b16 { %0, %1, %2, %3 }, [ %4 ];"
                 : "=r"(r[0]), "=r"(r[1]), "=r"(r[2]), "=r"(r[3]) : "r"(addr));
}
__device__ __forceinline__ void mma_bf16(float* c, const unsigned* a,
                                         unsigned b0, unsigned b1)
{
    asm volatile("mma.sync.aligned.m16n8k16.row.col.f32.bf16.bf16.f32 "
                 "{ %0, %1, %2, %3 }, { %4, %5, %6, %7 }, { %8, %9 }, { %0, %1, %2, %3 };"
                 : "+f"(c[0]), "+f"(c[1]), "+f"(c[2]), "+f"(c[3])
                 : "r"(a[0]), "r"(a[1]), "r"(a[2]), "r"(a[3]), "r"(b0), "r"(b1));
}
__device__ __forceinline__ void cp16(unsigned dst, const void* src)
{
    asm volatile("cp.async.cg.shared.global [ %0 ], [ %1 ], 16;" :: "r"(dst), "l"(src));
}
__device__ __forceinline__ void cpcommit()
{
    asm volatile("cp.async.commit_group;");
}
__device__ __forceinline__ void cpwait0()
{
    asm volatile("cp.async.wait_group 0;");
}
__device__ __forceinline__ void cpwait1()
{
    asm volatile("cp.async.wait_group 1;");
}

// ---------------------------------------------------------------------------
// GEMM (NT): 3-term emulated fp32, pre-split bf16, cp.async 2-stage.
// BM=128, BN=128, BK=32, warp tile 32x64 (round-11 config: 2 CTAs/SM).
// ---------------------------------------------------------------------------
__global__ void __launch_bounds__(256) gemm_bf16_pre(
    const __nv_bfloat16* __restrict__ Ah, const __nv_bfloat16* __restrict__ Al,
    const __nv_bfloat16* __restrict__ Bh, const __nv_bfloat16* __restrict__ Bl,
    float* __restrict__ C, int M, int N, int K)
{
    constexpr int BM = 128, BN = 128, BK = 32, LD = 40;
    constexpr int STG = 4 * 128 * LD;
    extern __shared__ __align__(16) char smraw[];
    __nv_bfloat16* sm = (__nv_bfloat16*)smraw;
    const unsigned smS = (unsigned)__cvta_generic_to_shared(sm);

    const int tid = threadIdx.x;
    const int m0 = blockIdx.y * BM;
    const int n0 = blockIdx.x * BN;
    const int w = tid >> 5;
    const int wm = w >> 1;
    const int wn = w & 1;

    wmma::fragment<wmma::accumulator, 16, 16, 16, float> acc[2][4];
#pragma unroll
    for (int i = 0; i < 2; i++)
#pragma unroll
        for (int j = 0; j < 4; j++)
            wmma::fill_fragment(acc[i][j], 0.0f);

    const int nk = K / BK;

    const __nv_bfloat16* srcs[4];
    srcs[0] = Ah; srcs[1] = Al; srcs[2] = Bh; srcs[3] = Bl;

#define LOAD_STAGE(stg, k0)                                                   \
    do {                                                                      \
        unsigned sb = smS + (unsigned)((stg) * STG * 2);                      \
        for (int arr = 0; arr < 4; arr++) {                                   \
            int g0 = (arr < 2) ? m0 : n0;                                     \
            const __nv_bfloat16* sp = srcs[arr];                              \
            for (int c = tid; c < 512; c += 256) {                            \
                int r = c >> 2;                                               \
                int coff = (c & 3) * 8;                                       \
                unsigned dst = sb + (unsigned)((arr * 128 * LD + r * LD + coff) * 2); \
                cp16(dst, sp + (size_t)(g0 + r) * K + (k0) + coff);           \
            }                                                                 \
        }                                                                     \
    } while (0)

    LOAD_STAGE(0, 0);
    cpcommit();

    for (int kt = 0; kt < nk; kt++) {
        if (kt + 1 < nk) {
            LOAD_STAGE((kt + 1) & 1, (kt + 1) * BK);
            cpcommit();
            cpwait1();
        } else {
            cpwait0();
        }
        __syncthreads();

        __nv_bfloat16* sAh = sm + (kt & 1) * STG;
        __nv_bfloat16* sAl = sAh + 128 * LD;
        __nv_bfloat16* sBh = sAl + 128 * LD;
        __nv_bfloat16* sBl = sBh + 128 * LD;

#pragma unroll
        for (int kk = 0; kk < BK; kk += 16) {
            wmma::fragment<wmma::matrix_a, 16, 16, 16, __nv_bfloat16, wmma::row_major> afh[2];
            wmma::fragment<wmma::matrix_a, 16, 16, 16, __nv_bfloat16, wmma::row_major> afl[2];
            wmma::fragment<wmma::matrix_b, 16, 16, 16, __nv_bfloat16, wmma::col_major> bfh[4];
            wmma::fragment<wmma::matrix_b, 16, 16, 16, __nv_bfloat16, wmma::col_major> bfl[4];
#pragma unroll
            for (int i = 0; i < 2; i++) {
                wmma::load_matrix_sync(afh[i], &sAh[(wm * 32 + i * 16) * LD + kk], LD);
                wmma::load_matrix_sync(afl[i], &sAl[(wm * 32 + i * 16) * LD + kk], LD);
            }
#pragma unroll
            for (int j = 0; j < 4; j++) {
                wmma::load_matrix_sync(bfh[j], &sBh[(wn * 64 + j * 16) * LD + kk], LD);
                wmma::load_matrix_sync(bfl[j], &sBl[(wn * 64 + j * 16) * LD + kk], LD);
            }
#pragma unroll
            for (int i = 0; i < 2; i++)
#pragma unroll
                for (int j = 0; j < 4; j++) {
                    wmma::mma_sync(acc[i][j], afh[i], bfl[j], acc[i][j]);
                    wmma::mma_sync(acc[i][j], afl[i], bfh[j], acc[i][j]);
                    wmma::mma_sync(acc[i][j], afh[i], bfh[j], acc[i][j]);
                }
        }
        __syncthreads();
    }
#undef LOAD_STAGE

#pragma unroll
    for (int i = 0; i < 2; i++)
#pragma unroll
        for (int j = 0; j < 4; j++)
            wmma::store_matrix_sync(
                C + (size_t)(m0 + wm * 32 + i * 16) * N + n0 + wn * 64 + j * 16,
                acc[i][j], N, wmma::mem_row_major);
}

// ---------------------------------------------------------------------------
// Fused RMSNorm + rope on q,k AND hi/lo bf16 pack of q,k,v.
// ---------------------------------------------------------------------------
__global__ void __launch_bounds__(512) norm_rope_pack_kernel(
    const float* __restrict__ qkv, const float* __restrict__ rope,
    __nv_bfloat16* __restrict__ qh, __nv_bfloat16* __restrict__ ql)
{
    const int bt = blockIdx.x;
    const int t = bt & (Tv - 1);
    const int warp = threadIdx.x >> 5;
    const int lane = threadIdx.x & 31;

    const size_t base = (size_t)bt * QKV_N + warp * HDv;
    float c = rope[t * 32 + lane];
    float s = rope[Tv * 32 + t * 32 + lane];

#pragma unroll
    for (int p = 0; p < 2; p++) {   // q, k
        const float* ptr = qkv + base + p * Cv;
        float x1 = ptr[lane];
        float x2 = ptr[lane + 32];
        float ss = x1 * x1 + x2 * x2;
#pragma unroll
        for (int off = 16; off; off >>= 1)
            ss += __shfl_xor_sync(0xffffffffu, ss, off);
        float r = rsqrtf(ss * (1.0f / 64.0f) + 1.1920929e-07f);
        x1 *= r;
        x2 *= r;
        float y1 = x1 * c + x2 * s;
        float y2 = -x1 * s + x2 * c;
        split1(y1, qh + base + p * Cv + lane, ql + base + p * Cv + lane);
        split1(y2, qh + base + p * Cv + lane + 32, ql + base + p * Cv + lane + 32);
    }
    {
        const float* ptr = qkv + base + 2 * Cv;
        float v1 = ptr[lane];
        float v2 = ptr[lane + 32];
        split1(v1, qh + base + 2 * Cv + lane, ql + base + 2 * Cv + lane);
        split1(v2, qh + base + 2 * Cv + lane + 32, ql + base + 2 * Cv + lane + 32);
    }
}

// ---------------------------------------------------------------------------
// Flash attention: raw mma 3xBF16, register S/O, pre-split inputs,
// cp.async 2-stage K/V. Epilogue writes y pre-split into ah/al (for proj).
// ---------------------------------------------------------------------------
__global__ void __launch_bounds__(256) flash_mma_kernel(
    const __nv_bfloat16* __restrict__ qh, const __nv_bfloat16* __restrict__ ql,
    __nv_bfloat16* __restrict__ yh, __nv_bfloat16* __restrict__ yl)
{
    constexpr int LDB = 72;
    constexpr int KVSTG = 4 * 64 * LDB;
    extern __shared__ __align__(16) char smraw[];
    __nv_bfloat16* Qh = (__nv_bfloat16*)smraw;
    __nv_bfloat16* Ql = Qh + 128 * LDB;
    __nv_bfloat16* KV = Ql + 128 * LDB;

    const int qt = gridDim.x - 1 - blockIdx.x;
    const int bh = blockIdx.y;
    const int b = bh / Hv;
    const int h = bh % Hv;
    const int tid = threadIdx.x;
    const int wid = tid >> 5;
    const int lane = tid & 31;
    const int gid = lane >> 2;
    const int tig = lane & 3;

    const size_t rowbase = (size_t)b * Tv;
    const int q0 = qt * 128;

    const int arow = (lane & 7) + 8 * ((lane >> 3) & 1);
    const int acolo = 8 * (lane >> 4);
    const int brow = (lane & 7) + 8 * (lane >> 4);
    const int bcolo = 8 * ((lane >> 3) & 1);

    const unsigned QhS = (unsigned)__cvta_generic_to_shared(Qh);
    const unsigned QlS = (unsigned)__cvta_generic_to_shared(Ql);
    const unsigned KVS = (unsigned)__cvta_generic_to_shared(KV);

    float sc[8][4];
    float oc[8][4];
    unsigned qa[4];
    unsigned qb[4];
    unsigned ka[4];
    unsigned kb[4];
    unsigned va[4];
    unsigned vb[4];
    unsigned pah[4][4];
    unsigned pal[4][4];
    float mrow[2];
    float lrow[2];

#define LOAD_KV(stg, jt)                                                      \
    do {                                                                      \
        unsigned sb = KVS + (unsigned)((stg) * KVSTG * 2);                    \
        const __nv_bfloat16* gkh = qh + (rowbase + (jt) * 64) * (size_t)QKV_N + Cv + h * HDv; \
        const __nv_bfloat16* gkl = ql + (rowbase + (jt) * 64) * (size_t)QKV_N + Cv + h * HDv; \
        for (int c = tid; c < 512; c += 256) {                                \
            int r = c >> 3;                                                   \
            int co = (c & 7) * 8;                                             \
            unsigned off = (unsigned)((r * LDB + co) * 2);                    \
            cp16(sb + off, gkh + (size_t)r * QKV_N + co);                     \
            cp16(sb + (unsigned)(64 * LDB * 2) + off, gkl + (size_t)r * QKV_N + co); \
            cp16(sb + (unsigned)(2 * 64 * LDB * 2) + off, gkh + (size_t)r * QKV_N + Cv + co); \
            cp16(sb + (unsigned)(3 * 64 * LDB * 2) + off, gkl + (size_t)r * QKV_N + Cv + co); \
        }                                                                     \
    } while (0)

    for (int c = tid; c < 1024; c += 256) {
        int r = c >> 3;
        int co = (c & 7) * 8;
        unsigned off = (unsigned)((r * LDB + co) * 2);
        cp16(QhS + off, qh + (rowbase + q0 + r) * (size_t)QKV_N + h * HDv + co);
        cp16(QlS + off, ql + (rowbase + q0 + r) * (size_t)QKV_N + h * HDv + co);
    }
    LOAD_KV(0, 0);
    cpcommit();

#pragma unroll
    for (int j = 0; j < 8; j++)
#pragma unroll
        for (int k = 0; k < 4; k++) oc[j][k] = 0.0f;

    mrow[0] = -1e30f;
    mrow[1] = -1e30f;
    lrow[0] = 0.0f;
    lrow[1] = 0.0f;
    const int r0g = q0 + wid * 16 + gid;
    const int r1g = r0g + 8;

    const int jt_max = 2 * qt + 1;
    for (int jt = 0; jt <= jt_max; jt++) {
        if (jt < jt_max) {
            LOAD_KV((jt + 1) & 1, jt + 1);
            cpcommit();
            cpwait1();
        } else {
            cpwait0();
        }
        __syncthreads();

        unsigned sb = KVS + (unsigned)((jt & 1) * KVSTG * 2);
        unsigned KhC = sb;
        unsigned KlC = sb + (unsigned)(64 * LDB * 2);
        unsigned VhC = sb + (unsigned)(2 * 64 * LDB * 2);
        unsigned VlC = sb + (unsigned)(3 * 64 * LDB * 2);

#pragma unroll
        for (int j = 0; j < 8; j++)
#pragma unroll
            for (int k = 0; k < 4; k++) sc[j][k] = 0.0f;

#pragma unroll
        for (int t = 0; t < 4; t++) {
            unsigned qoff = (unsigned)(((wid * 16 + arow) * LDB + t * 16 + acolo) * 2);
            ldsm4(QhS + qoff, qa);
            ldsm4(QlS + qoff, qb);
#pragma unroll
            for (int g = 0; g < 4; g++) {
                unsigned koff = (unsigned)(((g * 16 + brow) * LDB + t * 16 + bcolo) * 2);
                ldsm4(KhC + koff, ka);
                ldsm4(KlC + koff, kb);
                mma_bf16(sc[2 * g], qa, kb[0], kb[1]);
                mma_bf16(sc[2 * g], qb, ka[0], ka[1]);
                mma_bf16(sc[2 * g], qa, ka[0], ka[1]);
                mma_bf16(sc[2 * g + 1], qa, kb[2], kb[3]);
                mma_bf16(sc[2 * g + 1], qb, ka[2], ka[3]);
                mma_bf16(sc[2 * g + 1], qa, ka[2], ka[3]);
            }
        }

        const bool maskp = (jt >= 2 * qt);
        float mt0 = -1e30f;
        float mt1 = -1e30f;
#pragma unroll
        for (int j = 0; j < 8; j++) {
            int c0 = jt * 64 + j * 8 + tig * 2;
            sc[j][0] *= 0.125f;
            sc[j][1] *= 0.125f;
            sc[j][2] *= 0.125f;
            sc[j][3] *= 0.125f;
            if (maskp) {
                if (c0 > r0g) sc[j][0] = -1e30f;
                if (c0 + 1 > r0g) sc[j][1] = -1e30f;
                if (c0 > r1g) sc[j][2] = -1e30f;
                if (c0 + 1 > r1g) sc[j][3] = -1e30f;
            }
            mt0 = fmaxf(mt0, fmaxf(sc[j][0], sc[j][1]));
            mt1 = fmaxf(mt1, fmaxf(sc[j][2], sc[j][3]));
        }
        mt0 = fmaxf(mt0, __shfl_xor_sync(0xffffffffu, mt0, 1));
        mt0 = fmaxf(mt0, __shfl_xor_sync(0xffffffffu, mt0, 2));
        mt1 = fmaxf(mt1, __shfl_xor_sync(0xffffffffu, mt1, 1));
        mt1 = fmaxf(mt1, __shfl_xor_sync(0xffffffffu, mt1, 2));

        float mn0 = fmaxf(mrow[0], mt0);
        float mn1 = fmaxf(mrow[1], mt1);
        float corr0 = expf(mrow[0] - mn0);
        float corr1 = expf(mrow[1] - mn1);

        float s0 = 0.0f;
        float s1 = 0.0f;
#pragma unroll
        for (int t = 0; t < 4; t++) {
            float p00 = expf(sc[2 * t][0] - mn0);
            float p01 = expf(sc[2 * t][1] - mn0);
            float p02 = expf(sc[2 * t][2] - mn1);
            float p03 = expf(sc[2 * t][3] - mn1);
            float p10 = expf(sc[2 * t + 1][0] - mn0);
            float p11 = expf(sc[2 * t + 1][1] - mn0);
            float p12 = expf(sc[2 * t + 1][2] - mn1);
            float p13 = expf(sc[2 * t + 1][3] - mn1);
            s0 += p00 + p01 + p10 + p11;
            s1 += p02 + p03 + p12 + p13;
            packsplit(p00, p01, pah[t][0], pal[t][0]);
            packsplit(p02, p03, pah[t][1], pal[t][1]);
            packsplit(p10, p11, pah[t][2], pal[t][2]);
            packsplit(p12, p13, pah[t][3], pal[t][3]);
        }
        s0 += __shfl_xor_sync(0xffffffffu, s0, 1);
        s0 += __shfl_xor_sync(0xffffffffu, s0, 2);
        s1 += __shfl_xor_sync(0xffffffffu, s1, 1);
        s1 += __shfl_xor_sync(0xffffffffu, s1, 2);

        lrow[0] = lrow[0] * corr0 + s0;
        lrow[1] = lrow[1] * corr1 + s1;
        mrow[0] = mn0;
        mrow[1] = mn1;
#pragma unroll
        for (int j = 0; j < 8; j++) {
            oc[j][0] *= corr0;
            oc[j][1] *= corr0;
            oc[j][2] *= corr1;
            oc[j][3] *= corr1;
        }

#pragma unroll
        for (int t = 0; t < 4; t++) {
#pragma unroll
            for (int n = 0; n < 4; n++) {
                unsigned voff = (unsigned)(((t * 16 + arow) * LDB + n * 16 + acolo) * 2);
                ldsm4t(VhC + voff, va);
                ldsm4t(VlC + voff, vb);
                mma_bf16(oc[2 * n], pah[t], vb[0], vb[1]);
                mma_bf16(oc[2 * n], pal[t], va[0], va[1]);
                mma_bf16(oc[2 * n], pah[t], va[0], va[1]);
                mma_bf16(oc[2 * n + 1], pah[t], vb[2], vb[3]);
                mma_bf16(oc[2 * n + 1], pal[t], va[2], va[3]);
                mma_bf16(oc[2 * n + 1], pah[t], va[2], va[3]);
            }
        }
        __syncthreads();
    }
#undef LOAD_KV

    // Epilogue: normalize and write y pre-split (hi/lo) for the proj GEMM.
    float i0 = 1.0f / lrow[0];
    float i1 = 1.0f / lrow[1];
#pragma unroll
    for (int j = 0; j < 8; j++) {
        int col = h * HDv + j * 8 + tig * 2;
        size_t idx0 = (rowbase + r0g) * (size_t)Cv + col;
        size_t idx1 = (rowbase + r1g) * (size_t)Cv + col;
        split1(oc[j][0] * i0, yh + idx0, yl + idx0);
        split1(oc[j][1] * i0, yh + idx0 + 1, yl + idx0 + 1);
        split1(oc[j][2] * i1, yh + idx1, yl + idx1);
        split1(oc[j][3] * i1, yh + idx1 + 1, yl + idx1 + 1);
    }
}

// ---------------------------------------------------------------------------
extern "C" void kernel_launch(void* const* d_in, const int* in_sizes, int n_in,
                              void* d_out, int out_size)
{
    const float* x = (const float*)d_in[0];
    const float* w_attn = (const float*)d_in[1];
    const float* w_proj = (const float*)d_in[2];
    float* out = (float*)d_out;

    float* qkv_p = nullptr;
    float* rope_p = nullptr;
    __nv_bfloat16* ah_p = nullptr;
    __nv_bfloat16* al_p = nullptr;
    __nv_bfloat16* wh_p = nullptr;
    __nv_bfloat16* wl_p = nullptr;
    __nv_bfloat16* qh_p = nullptr;
    __nv_bfloat16* ql_p = nullptr;
    cudaGetSymbolAddress((void**)&qkv_p, g_qkv);
    cudaGetSymbolAddress((void**)&rope_p, g_rope);
    cudaGetSymbolAddress((void**)&ah_p, g_ah);
    cudaGetSymbolAddress((void**)&al_p, g_al);
    cudaGetSymbolAddress((void**)&wh_p, g_wh);
    cudaGetSymbolAddress((void**)&wl_p, g_wl);
    cudaGetSymbolAddress((void**)&qh_p, g_qkvh);
    cudaGetSymbolAddress((void**)&ql_p, g_qkvl);

    const int GEMM_SMEM = 2 * 4 * 128 * 40 * (int)sizeof(__nv_bfloat16);  // 81920 B
    cudaFuncSetAttribute(gemm_bf16_pre, cudaFuncAttributeMaxDynamicSharedMemorySize, GEMM_SMEM);

    rope_table_kernel<<<(Tv * 32 + 255) / 256, 256>>>(rope_p);

    pack_split_kernel<<<(Mv * Cv / 4 + 255) / 256, 256>>>(x, ah_p, al_p, Mv * Cv / 4);
    pack_split_kernel<<<(QKV_N * Cv / 4 + 255) / 256, 256>>>(w_attn, wh_p, wl_p, QKV_N * Cv / 4);
    pack_split_kernel<<<(Cv * Cv / 4 + 255) / 256, 256>>>(
        w_proj, wh_p + QKV_N * Cv, wl_p + QKV_N * Cv, Cv * Cv / 4);

    // qkv = x @ w_attn^T
    gemm_bf16_pre<<<dim3(QKV_N / 128, Mv / 128), 256, GEMM_SMEM>>>(
        ah_p, al_p, wh_p, wl_p, qkv_p, Mv, QKV_N, Cv);

    // norm + rope + split pack of q,k,v
    norm_rope_pack_kernel<<<Mv, 512>>>(qkv_p, rope_p, qh_p, ql_p);

    // flash -> writes y pre-split into ah/al
    const int FLASH_SMEM = (2 * 128 * 72 + 8 * 64 * 72) * (int)sizeof(__nv_bfloat16);  // 110592 B
    cudaFuncSetAttribute(flash_mma_kernel, cudaFuncAttributeMaxDynamicSharedMemorySize, FLASH_SMEM);
    flash_mma_kernel<<<dim3(Tv / 128, Bv * Hv), 256, FLASH_SMEM>>>(qh_p, ql_p, ah_p, al_p);

    // out = y @ w_proj^T
    gemm_bf16_pre<<<dim3(Cv / 128, Mv / 128), 256, GEMM_SMEM>>>(
        ah_p, al_p, wh_p + QKV_N * Cv, wl_p + QKV_N * Cv, out, Mv, Cv, Cv);
}